// round 6
// baseline (speedup 1.0000x reference)
#include <cuda_runtime.h>
#include <cuda_bf16.h>
#include <cstdint>

#define NN 50000
#define NE 640000
#define DD 128
#define NCLS 64

// ---------------- scratch (device globals; float4 => guaranteed 16B alignment) ----------------
__device__ float4 g_bufA[(size_t)NN * 32];   // 50000 x 128 floats
__device__ float4 g_bufB[(size_t)NN * 32];
__device__ int    g_cnt[NN];
__device__ int    g_off[NN + 1];
__device__ int    g_cur[NN];
__device__ float  g_dinv[NN];
__device__ int    g_col[NE];
__device__ int    g_src[NE];
__device__ int    g_dst[NE];

// ---------------- zero counters ----------------
__global__ void zero_cnt_kernel() {
    int i = blockIdx.x * blockDim.x + threadIdx.x;
    if (i < NN) g_cnt[i] = 0;
}

// ---------------- fused: dtype-detect + normalize + histogram ----------------
// int64 values < 2^31 have zero hi (odd) 32-bit words. Each block samples the SAME
// 32 fixed odd words (in-bounds under both layouts); any nonzero => int32 layout.
// False classification prob ~ (1/50000)^32 ~ 0. Same verdict in every block.
__global__ void edges_kernel(const unsigned int* __restrict__ raw) {
    __shared__ int s_is64;
    if (threadIdx.x < 32) {
        size_t k = (size_t)threadIdx.x * (NE / 32);
        unsigned int hi = raw[2 * k + 1];
        unsigned int any = __ballot_sync(0xffffffffu, hi != 0u);
        if (threadIdx.x == 0) s_is64 = (any == 0u);
    }
    __syncthreads();
    int is64 = s_is64;
    int e = blockIdx.x * blockDim.x + threadIdx.x;
    if (e >= NE) return;
    const int* raw32 = (const int*)raw;
    int s, d;
    if (is64) {
        s = raw32[2 * (size_t)e];            // lo word of src int64
        d = raw32[2 * ((size_t)NE + e)];     // lo word of dst int64
    } else {
        s = raw32[e];
        d = raw32[NE + e];
    }
    s = min(max(s, 0), NN - 1);
    d = min(max(d, 0), NN - 1);
    g_src[e] = s;
    g_dst[e] = d;
    atomicAdd(&g_cnt[d], 1);
}

// ---------------- single-block exclusive scan; also emits dinv and cursor ----------------
__global__ void scan_kernel() {
    __shared__ int wsum[32];
    int lane = threadIdx.x & 31;
    int wid  = threadIdx.x >> 5;
    int carry = 0;
    for (int base = 0; base < NN; base += 1024) {
        int i = base + threadIdx.x;
        int v = (i < NN) ? g_cnt[i] : 0;
        int inc = v;
        #pragma unroll
        for (int d = 1; d < 32; d <<= 1) {
            int t = __shfl_up_sync(0xffffffffu, inc, d);
            if (lane >= d) inc += t;
        }
        if (lane == 31) wsum[wid] = inc;
        __syncthreads();
        if (wid == 0) {
            int s = wsum[lane];
            #pragma unroll
            for (int d = 1; d < 32; d <<= 1) {
                int t = __shfl_up_sync(0xffffffffu, s, d);
                if (lane >= d) s += t;
            }
            wsum[lane] = s;
        }
        __syncthreads();
        int add  = carry + (wid > 0 ? wsum[wid - 1] : 0);
        int excl = add + inc - v;
        if (i < NN) {
            g_off[i]  = excl;
            g_cur[i]  = excl;
            g_dinv[i] = rsqrtf((float)(v + 1));  // +1 self-loop
        }
        carry += wsum[31];
        __syncthreads();
    }
    if (threadIdx.x == 0) g_off[NN] = carry;
}

__global__ void fill_kernel() {
    int e = blockIdx.x * blockDim.x + threadIdx.x;
    if (e < NE) {
        int p = atomicAdd(&g_cur[g_dst[e]], 1);
        g_col[p] = g_src[e];
    }
}

// ---------------- sparse propagate: out[i] = dinv[i]*( sum_e dinv[src]*X[src] + dinv[i]*X[i] )
// one warp per node; lane l owns dims [4l,4l+4). FROM_X reads external x, else g_bufB.
// Always writes g_bufA.
template<bool FROM_X>
__global__ void prop_kernel(const float* __restrict__ xin) {
    int warp = (blockIdx.x * blockDim.x + threadIdx.x) >> 5;
    int lane = threadIdx.x & 31;
    if (warp >= NN) return;
    const float4* X4 = FROM_X ? (const float4*)xin : (const float4*)g_bufB;
    int i = warp;
    float di = g_dinv[i];
    float4 v = X4[(size_t)i * 32 + lane];
    float ax = di * v.x, ay = di * v.y, az = di * v.z, aw = di * v.w;
    int e  = g_off[i];
    int e1 = g_off[i + 1];
    for (; e + 4 <= e1; e += 4) {
        int s0 = g_col[e + 0], s1 = g_col[e + 1], s2 = g_col[e + 2], s3 = g_col[e + 3];
        float w0 = g_dinv[s0], w1 = g_dinv[s1], w2 = g_dinv[s2], w3 = g_dinv[s3];
        float4 v0 = X4[(size_t)s0 * 32 + lane];
        float4 v1 = X4[(size_t)s1 * 32 + lane];
        float4 v2 = X4[(size_t)s2 * 32 + lane];
        float4 v3 = X4[(size_t)s3 * 32 + lane];
        ax += w0 * v0.x + w1 * v1.x + w2 * v2.x + w3 * v3.x;
        ay += w0 * v0.y + w1 * v1.y + w2 * v2.y + w3 * v3.y;
        az += w0 * v0.z + w1 * v1.z + w2 * v2.z + w3 * v3.z;
        aw += w0 * v0.w + w1 * v1.w + w2 * v2.w + w3 * v3.w;
    }
    for (; e < e1; ++e) {
        int s = g_col[e];
        float w = g_dinv[s];
        float4 vv = X4[(size_t)s * 32 + lane];
        ax += w * vv.x; ay += w * vv.y; az += w * vv.z; aw += w * vv.w;
    }
    float4 o;
    o.x = ax * di; o.y = ay * di; o.z = az * di; o.w = aw * di;
    g_bufA[(size_t)i * 32 + lane] = o;
}

// ---------------- dense fp32 GEMM with packed f32x2 FFMA2 ----------------
// C[M,N] = A[M,128] @ W[128,N] + bias (opt relu). BK=16 chunks. 256 threads = 16x16.
// A staged transposed [k][row] (stride 130: float2-aligned, conflict-free both ways).
// W staged as duplicated pairs {w,w} so b-broadcast is one LDS.64.
// Each thread: 4 row-pairs x (N/16) cols of packed accumulators.
// SRC_B: A = g_bufB else g_bufA.  TO_OUT: C = outp else g_bufB.
template<int N, bool RELU, bool SRC_B, bool TO_OUT>
__global__ void gemm_kernel(const float* __restrict__ W, const float* __restrict__ bias,
                            float* __restrict__ outp) {
    const float4* A4 = SRC_B ? (const float4*)g_bufB : (const float4*)g_bufA;
    float* C = TO_OUT ? outp : (float*)g_bufB;

    constexpr int BK = 16;
    __shared__ alignas(16) float  Ast[BK * 130];    // transposed A chunk [k][row]
    __shared__ alignas(16) float2 Wd[BK * N];       // duplicated W pairs  [k][col]

    int m0 = blockIdx.x * 128;
    int tx = threadIdx.x & 15;
    int ty = threadIdx.x >> 4;
    constexpr int TNc = N / 16;

    unsigned long long acc[4][TNc];
    #pragma unroll
    for (int r = 0; r < 4; ++r)
        #pragma unroll
        for (int c = 0; c < TNc; ++c) acc[r][c] = 0ull;

    for (int kb = 0; kb < 128; kb += BK) {
        // A chunk: 128 rows x 16 k = 512 float4; transpose into Ast
        #pragma unroll
        for (int f = threadIdx.x; f < 512; f += 256) {
            int row = f >> 2, j = f & 3;
            float4 v = make_float4(0.f, 0.f, 0.f, 0.f);
            int gr = m0 + row;
            if (gr < NN) v = A4[(size_t)gr * 32 + (kb >> 2) + j];
            Ast[(4 * j + 0) * 130 + row] = v.x;
            Ast[(4 * j + 1) * 130 + row] = v.y;
            Ast[(4 * j + 2) * 130 + row] = v.z;
            Ast[(4 * j + 3) * 130 + row] = v.w;
        }
        // W chunk: duplicate each value into a pair (N is a power of two: >> and & fold)
        #pragma unroll
        for (int f = threadIdx.x; f < BK * N; f += 256) {
            int k = f / N, j = f & (N - 1);
            float w = W[(kb + k) * N + j];
            Wd[k * N + j] = make_float2(w, w);
        }
        __syncthreads();

        #pragma unroll
        for (int k = 0; k < BK; ++k) {
            unsigned long long a2[4], b2[TNc];
            #pragma unroll
            for (int r = 0; r < 4; ++r)
                a2[r] = *(const unsigned long long*)&Ast[k * 130 + ty * 8 + 2 * r];
            #pragma unroll
            for (int c = 0; c < TNc; ++c)
                b2[c] = *(const unsigned long long*)&Wd[k * N + tx + 16 * c];
            #pragma unroll
            for (int r = 0; r < 4; ++r)
                #pragma unroll
                for (int c = 0; c < TNc; ++c)
                    asm("fma.rn.f32x2 %0, %1, %2, %0;"
                        : "+l"(acc[r][c]) : "l"(a2[r]), "l"(b2[c]));
        }
        __syncthreads();
    }

    #pragma unroll
    for (int r = 0; r < 4; ++r) {
        int gr0 = m0 + ty * 8 + 2 * r;
        #pragma unroll
        for (int c = 0; c < TNc; ++c) {
            int col = tx + 16 * c;
            float lo = __uint_as_float((unsigned int)(acc[r][c] & 0xffffffffull));
            float hi = __uint_as_float((unsigned int)(acc[r][c] >> 32));
            float bb = bias[col];
            lo += bb; hi += bb;
            if (RELU) { lo = fmaxf(lo, 0.f); hi = fmaxf(hi, 0.f); }
            if (gr0 < NN)     C[(size_t)gr0 * N + col]       = lo;
            if (gr0 + 1 < NN) C[(size_t)(gr0 + 1) * N + col] = hi;
        }
    }
}

// ---------------- launch ----------------
extern "C" void kernel_launch(void* const* d_in, const int* in_sizes, int n_in,
                              void* d_out, int out_size) {
    const float* x  = (const float*)d_in[0];
    const float* W1 = (const float*)d_in[2];
    const float* b1 = (const float*)d_in[3];
    const float* W2 = (const float*)d_in[4];
    const float* b2 = (const float*)d_in[5];
    const float* Wl = (const float*)d_in[6];
    const float* bl = (const float*)d_in[7];
    float*       out = (float*)d_out;

    // CSR build
    zero_cnt_kernel<<<(NN + 255) / 256, 256>>>();
    edges_kernel<<<(NE + 255) / 256, 256>>>((const unsigned int*)d_in[1]);
    scan_kernel<<<1, 1024>>>();
    fill_kernel<<<(NE + 255) / 256, 256>>>();

    dim3 pgrid((NN + 7) / 8);
    dim3 ggrid((NN + 127) / 128);

    // layer 1: propagate(x) -> bufA ; bufA @ W1 + b1, relu -> bufB
    prop_kernel<true><<<pgrid, 256>>>(x);
    gemm_kernel<128, true, false, false><<<ggrid, 256>>>(W1, b1, nullptr);
    // layer 2: propagate(bufB) -> bufA ; bufA @ W2 + b2, relu -> bufB
    prop_kernel<false><<<pgrid, 256>>>(nullptr);
    gemm_kernel<128, true, false, false><<<ggrid, 256>>>(W2, b2, nullptr);
    // head: bufB @ Wl + bl -> out
    gemm_kernel<64, false, true, true><<<ggrid, 256>>>(Wl, bl, out);
}

// round 8
// speedup vs baseline: 1.4791x; 1.4791x over previous
#include <cuda_runtime.h>
#include <cuda_bf16.h>
#include <cstdint>

#define NN 50000
#define NE 640000
#define DD 128
#define NCLS 64

// ---------------- scratch (device globals) ----------------
__device__ uint4  g_Ah[(size_t)NN * 16];   // [NN][128] bf16 hi  (row = 256B = 16 uint4)
__device__ uint4  g_Al[(size_t)NN * 16];   // [NN][128] bf16 lo
__device__ float4 g_bufB[(size_t)NN * 32]; // [NN][128] f32 (layer outputs)
__device__ uint4  g_W1h[128 * 16], g_W1l[128 * 16];  // W1^T [n][k] bf16
__device__ uint4  g_W2h[128 * 16], g_W2l[128 * 16];  // W2^T
__device__ uint4  g_W3h[64 * 16],  g_W3l[64 * 16];   // Wl^T [64][128]
__device__ int    g_cnt[NN];
__device__ int    g_off[NN + 1];
__device__ int    g_cur[NN];
__device__ float  g_dinv[NN];
__device__ int    g_col[NE];
__device__ int    g_src[NE];
__device__ int    g_dst[NE];

// ---------------- helpers ----------------
__device__ __forceinline__ uint32_t smem_u32(const void* p) {
    uint32_t a;
    asm("{ .reg .u64 t; cvta.to.shared.u64 t, %1; cvt.u32.u64 %0, t; }" : "=r"(a) : "l"(p));
    return a;
}
__device__ __forceinline__ void ldsm_x4(uint32_t& r0, uint32_t& r1, uint32_t& r2, uint32_t& r3,
                                        uint32_t addr) {
    asm volatile("ldmatrix.sync.aligned.m8n8.x4.shared.b16 {%0,%1,%2,%3}, [%4];"
                 : "=r"(r0), "=r"(r1), "=r"(r2), "=r"(r3) : "r"(addr));
}
__device__ __forceinline__ void mma_bf16(float* c, uint32_t a0, uint32_t a1, uint32_t a2,
                                         uint32_t a3, uint32_t b0, uint32_t b1) {
    asm volatile(
        "mma.sync.aligned.m16n8k16.row.col.f32.bf16.bf16.f32 "
        "{%0,%1,%2,%3}, {%4,%5,%6,%7}, {%8,%9}, {%0,%1,%2,%3};"
        : "+f"(c[0]), "+f"(c[1]), "+f"(c[2]), "+f"(c[3])
        : "r"(a0), "r"(a1), "r"(a2), "r"(a3), "r"(b0), "r"(b1));
}

// ---------------- CSR build (verified R6) ----------------
__global__ void zero_cnt_kernel() {
    int i = blockIdx.x * blockDim.x + threadIdx.x;
    if (i < NN) g_cnt[i] = 0;
}

__global__ void edges_kernel(const unsigned int* __restrict__ raw) {
    __shared__ int s_is64;
    if (threadIdx.x < 32) {
        size_t k = (size_t)threadIdx.x * (NE / 32);
        unsigned int hi = raw[2 * k + 1];
        unsigned int any = __ballot_sync(0xffffffffu, hi != 0u);
        if (threadIdx.x == 0) s_is64 = (any == 0u);
    }
    __syncthreads();
    int is64 = s_is64;
    int e = blockIdx.x * blockDim.x + threadIdx.x;
    if (e >= NE) return;
    const int* raw32 = (const int*)raw;
    int s, d;
    if (is64) { s = raw32[2 * (size_t)e]; d = raw32[2 * ((size_t)NE + e)]; }
    else      { s = raw32[e];             d = raw32[NE + e]; }
    s = min(max(s, 0), NN - 1);
    d = min(max(d, 0), NN - 1);
    g_src[e] = s;
    g_dst[e] = d;
    atomicAdd(&g_cnt[d], 1);
}

__global__ void scan_kernel() {
    __shared__ int wsum[32];
    int lane = threadIdx.x & 31;
    int wid  = threadIdx.x >> 5;
    int carry = 0;
    for (int base = 0; base < NN; base += 1024) {
        int i = base + threadIdx.x;
        int v = (i < NN) ? g_cnt[i] : 0;
        int inc = v;
        #pragma unroll
        for (int d = 1; d < 32; d <<= 1) {
            int t = __shfl_up_sync(0xffffffffu, inc, d);
            if (lane >= d) inc += t;
        }
        if (lane == 31) wsum[wid] = inc;
        __syncthreads();
        if (wid == 0) {
            int s = wsum[lane];
            #pragma unroll
            for (int d = 1; d < 32; d <<= 1) {
                int t = __shfl_up_sync(0xffffffffu, s, d);
                if (lane >= d) s += t;
            }
            wsum[lane] = s;
        }
        __syncthreads();
        int add  = carry + (wid > 0 ? wsum[wid - 1] : 0);
        int excl = add + inc - v;
        if (i < NN) {
            g_off[i]  = excl;
            g_cur[i]  = excl;
            g_dinv[i] = rsqrtf((float)(v + 1));
        }
        carry += wsum[31];
        __syncthreads();
    }
    if (threadIdx.x == 0) g_off[NN] = carry;
}

__global__ void fill_kernel() {
    int e = blockIdx.x * blockDim.x + threadIdx.x;
    if (e < NE) {
        int p = atomicAdd(&g_cur[g_dst[e]], 1);
        g_col[p] = g_src[e];
    }
}

// ---------------- weight split: W[k][n] f32 -> W^T[n][k] bf16 hi/lo ----------------
__global__ void split_w_kernel(const float* __restrict__ W1, const float* __restrict__ W2,
                               const float* __restrict__ W3) {
    int i = blockIdx.x * blockDim.x + threadIdx.x;
    float v; __nv_bfloat16* dh; __nv_bfloat16* dl; int n, k;
    if (i < 16384) {
        v = W1[i]; k = i >> 7; n = i & 127;
        dh = (__nv_bfloat16*)g_W1h; dl = (__nv_bfloat16*)g_W1l;
    } else if (i < 32768) {
        int j = i - 16384;
        v = W2[j]; k = j >> 7; n = j & 127;
        dh = (__nv_bfloat16*)g_W2h; dl = (__nv_bfloat16*)g_W2l;
    } else if (i < 40960) {
        int j = i - 32768;
        v = W3[j]; k = j >> 6; n = j & 63;
        dh = (__nv_bfloat16*)g_W3h; dl = (__nv_bfloat16*)g_W3l;
    } else return;
    __nv_bfloat16 h = __float2bfloat16(v);
    __nv_bfloat16 l = __float2bfloat16(v - __bfloat162float(h));
    dh[n * 128 + k] = h;
    dl[n * 128 + k] = l;
}

// ---------------- sparse propagate -> bf16 hi/lo split output ----------------
// out[i] = dinv[i]*( sum_e dinv[src]*X[src] + dinv[i]*X[i] ); writes g_Ah/g_Al.
template<bool FROM_X>
__global__ void prop_kernel(const float* __restrict__ xin) {
    int warp = (blockIdx.x * blockDim.x + threadIdx.x) >> 5;
    int lane = threadIdx.x & 31;
    if (warp >= NN) return;
    const float4* X4 = FROM_X ? (const float4*)xin : (const float4*)g_bufB;
    int i = warp;
    float di = g_dinv[i];
    float4 v = X4[(size_t)i * 32 + lane];
    float ax = di * v.x, ay = di * v.y, az = di * v.z, aw = di * v.w;
    int e  = g_off[i];
    int e1 = g_off[i + 1];
    for (; e + 4 <= e1; e += 4) {
        int s0 = g_col[e + 0], s1 = g_col[e + 1], s2 = g_col[e + 2], s3 = g_col[e + 3];
        float w0 = g_dinv[s0], w1 = g_dinv[s1], w2 = g_dinv[s2], w3 = g_dinv[s3];
        float4 v0 = X4[(size_t)s0 * 32 + lane];
        float4 v1 = X4[(size_t)s1 * 32 + lane];
        float4 v2 = X4[(size_t)s2 * 32 + lane];
        float4 v3 = X4[(size_t)s3 * 32 + lane];
        ax += w0 * v0.x + w1 * v1.x + w2 * v2.x + w3 * v3.x;
        ay += w0 * v0.y + w1 * v1.y + w2 * v2.y + w3 * v3.y;
        az += w0 * v0.z + w1 * v1.z + w2 * v2.z + w3 * v3.z;
        aw += w0 * v0.w + w1 * v1.w + w2 * v2.w + w3 * v3.w;
    }
    for (; e < e1; ++e) {
        int s = g_col[e];
        float w = g_dinv[s];
        float4 vv = X4[(size_t)s * 32 + lane];
        ax += w * vv.x; ay += w * vv.y; az += w * vv.z; aw += w * vv.w;
    }
    ax *= di; ay *= di; az *= di; aw *= di;
    __nv_bfloat16 hx = __float2bfloat16(ax), hy = __float2bfloat16(ay);
    __nv_bfloat16 hz = __float2bfloat16(az), hw = __float2bfloat16(aw);
    __nv_bfloat16 lx = __float2bfloat16(ax - __bfloat162float(hx));
    __nv_bfloat16 ly = __float2bfloat16(ay - __bfloat162float(hy));
    __nv_bfloat16 lz = __float2bfloat16(az - __bfloat162float(hz));
    __nv_bfloat16 lw = __float2bfloat16(aw - __bfloat162float(hw));
    uint2 hv, lv;
    hv.x = ((uint32_t)__bfloat16_as_ushort(hy) << 16) | __bfloat16_as_ushort(hx);
    hv.y = ((uint32_t)__bfloat16_as_ushort(hw) << 16) | __bfloat16_as_ushort(hz);
    lv.x = ((uint32_t)__bfloat16_as_ushort(ly) << 16) | __bfloat16_as_ushort(lx);
    lv.y = ((uint32_t)__bfloat16_as_ushort(lw) << 16) | __bfloat16_as_ushort(lz);
    ((uint2*)g_Ah)[(size_t)i * 32 + lane] = hv;
    ((uint2*)g_Al)[(size_t)i * 32 + lane] = lv;
}

// ---------------- HMMA bf16 3-term GEMM ----------------
// C[M,N] = A[M,128]@W[128,N] + bias (opt relu); D = Ah*Bh + Al*Bh + Ah*Bl (fp32 acc).
// A: g_Ah/g_Al [M][128] bf16. B: g_W{LAY}h/l [n][128] bf16 (W^T). M-tile 128, 4 K-chunks
// of 32, 256 threads (8 warps x m16 strips). XOR-swizzled smem, ldmatrix + mma.sync.
// OUT: 0 = f32 g_bufB, 1 = bf16 split g_Ah/g_Al, 2 = f32 outp.
template<int N, bool RELU, int OUT, int LAY>
__global__ void __launch_bounds__(256) mma_gemm(const float* __restrict__ bias,
                                                float* __restrict__ outp) {
    constexpr int NT = N / 8;
    __shared__ uint4 sAh[128 * 4], sAl[128 * 4];
    __shared__ uint4 sBh[N * 4],   sBl[N * 4];

    const uint4* Wh = (LAY == 1) ? g_W1h : (LAY == 2) ? g_W2h : g_W3h;
    const uint4* Wl = (LAY == 1) ? g_W1l : (LAY == 2) ? g_W2l : g_W3l;

    int tid = threadIdx.x;
    int wid = tid >> 5;
    int lid = tid & 31;
    int m0  = blockIdx.x * 128;

    float acc[NT][4];
    #pragma unroll
    for (int t = 0; t < NT; ++t)
        #pragma unroll
        for (int j = 0; j < 4; ++j) acc[t][j] = 0.f;

    uint32_t sAh_b = smem_u32(sAh), sAl_b = smem_u32(sAl);
    uint32_t sBh_b = smem_u32(sBh), sBl_b = smem_u32(sBl);

    // ldmatrix lane-address constants (swizzle: unit = row*4 + (ch ^ ((row>>1)&3)))
    uint32_t a_row  = lid & 15;
    uint32_t a_half = lid >> 4;
    uint32_t a_x    = (a_row >> 1) & 3;
    uint32_t a_base = (wid * 16 + a_row) * 64;
    uint32_t b_c    = (lid & 7) + ((lid >> 4) & 1) * 8;
    uint32_t b_half = (lid >> 3) & 1;
    uint32_t b_x    = (b_c >> 1) & 3;
    uint32_t b_base = b_c * 64;

    for (int c = 0; c < 4; ++c) {
        // ---- stage A chunk (128 rows x 32 k bf16, hi+lo) ----
        #pragma unroll
        for (int f = tid; f < 128 * 4; f += 256) {
            int row = f >> 2, ch = f & 3;
            int gr = m0 + row;
            uint4 vh = make_uint4(0, 0, 0, 0), vl = vh;
            if (gr < NN) {
                size_t gi = (size_t)gr * 16 + c * 4 + ch;
                vh = g_Ah[gi]; vl = g_Al[gi];
            }
            int du = row * 4 + (ch ^ ((row >> 1) & 3));
            sAh[du] = vh; sAl[du] = vl;
        }
        // ---- stage B chunk (N rows x 32 k) ----
        #pragma unroll
        for (int f = tid; f < N * 4; f += 256) {
            int row = f >> 2, ch = f & 3;
            size_t gi = (size_t)row * 16 + c * 4 + ch;
            int du = row * 4 + (ch ^ ((row >> 1) & 3));
            sBh[du] = Wh[gi]; sBl[du] = Wl[gi];
        }
        __syncthreads();

        #pragma unroll
        for (int ks = 0; ks < 2; ++ks) {
            uint32_t aoff = a_base + (((ks * 2 + a_half) ^ a_x) << 4);
            uint32_t ah0, ah1, ah2, ah3, al0, al1, al2, al3;
            ldsm_x4(ah0, ah1, ah2, ah3, sAh_b + aoff);
            ldsm_x4(al0, al1, al2, al3, sAl_b + aoff);
            #pragma unroll
            for (int jp = 0; jp < NT / 2; ++jp) {
                uint32_t boff = jp * 1024 + b_base + (((ks * 2 + b_half) ^ b_x) << 4);
                uint32_t bh0, bh1, bh2, bh3, bl0, bl1, bl2, bl3;
                ldsm_x4(bh0, bh1, bh2, bh3, sBh_b + boff);
                mma_bf16(acc[2 * jp],     ah0, ah1, ah2, ah3, bh0, bh1);
                mma_bf16(acc[2 * jp + 1], ah0, ah1, ah2, ah3, bh2, bh3);
                mma_bf16(acc[2 * jp],     al0, al1, al2, al3, bh0, bh1);
                mma_bf16(acc[2 * jp + 1], al0, al1, al2, al3, bh2, bh3);
                ldsm_x4(bl0, bl1, bl2, bl3, sBl_b + boff);
                mma_bf16(acc[2 * jp],     ah0, ah1, ah2, ah3, bl0, bl1);
                mma_bf16(acc[2 * jp + 1], ah0, ah1, ah2, ah3, bl2, bl3);
            }
        }
        __syncthreads();
    }

    // ---- epilogue ----
    int g = lid >> 2, q = lid & 3;
    int r0 = m0 + wid * 16 + g;
    int r1 = r0 + 8;
    #pragma unroll
    for (int nt = 0; nt < NT; ++nt) {
        int col = nt * 8 + 2 * q;
        float2 bb = *(const float2*)&bias[col];
        float v0 = acc[nt][0] + bb.x, v1 = acc[nt][1] + bb.y;
        float v2 = acc[nt][2] + bb.x, v3 = acc[nt][3] + bb.y;
        if (RELU) {
            v0 = fmaxf(v0, 0.f); v1 = fmaxf(v1, 0.f);
            v2 = fmaxf(v2, 0.f); v3 = fmaxf(v3, 0.f);
        }
        if (OUT == 1) {
            __nv_bfloat16 h0 = __float2bfloat16(v0), h1 = __float2bfloat16(v1);
            __nv_bfloat16 h2 = __float2bfloat16(v2), h3 = __float2bfloat16(v3);
            ushort2 hp0, hp1, lp0, lp1;
            hp0.x = __bfloat16_as_ushort(h0); hp0.y = __bfloat16_as_ushort(h1);
            hp1.x = __bfloat16_as_ushort(h2); hp1.y = __bfloat16_as_ushort(h3);
            lp0.x = __bfloat16_as_ushort(__float2bfloat16(v0 - __bfloat162float(h0)));
            lp0.y = __bfloat16_as_ushort(__float2bfloat16(v1 - __bfloat162float(h1)));
            lp1.x = __bfloat16_as_ushort(__float2bfloat16(v2 - __bfloat162float(h2)));
            lp1.y = __bfloat16_as_ushort(__float2bfloat16(v3 - __bfloat162float(h3)));
            if (r0 < NN) {
                *(ushort2*)((__nv_bfloat16*)g_Ah + (size_t)r0 * 128 + col) = hp0;
                *(ushort2*)((__nv_bfloat16*)g_Al + (size_t)r0 * 128 + col) = lp0;
            }
            if (r1 < NN) {
                *(ushort2*)((__nv_bfloat16*)g_Ah + (size_t)r1 * 128 + col) = hp1;
                *(ushort2*)((__nv_bfloat16*)g_Al + (size_t)r1 * 128 + col) = lp1;
            }
        } else {
            float* C = (OUT == 2) ? outp : (float*)g_bufB;
            if (r0 < NN) *(float2*)&C[(size_t)r0 * N + col] = make_float2(v0, v1);
            if (r1 < NN) *(float2*)&C[(size_t)r1 * N + col] = make_float2(v2, v3);
        }
    }
}

// ---------------- launch ----------------
extern "C" void kernel_launch(void* const* d_in, const int* in_sizes, int n_in,
                              void* d_out, int out_size) {
    const float* x  = (const float*)d_in[0];
    const float* W1 = (const float*)d_in[2];
    const float* b1 = (const float*)d_in[3];
    const float* W2 = (const float*)d_in[4];
    const float* b2 = (const float*)d_in[5];
    const float* Wl = (const float*)d_in[6];
    const float* bl = (const float*)d_in[7];
    float*       out = (float*)d_out;

    // CSR build + weight split
    zero_cnt_kernel<<<(NN + 255) / 256, 256>>>();
    edges_kernel<<<(NE + 255) / 256, 256>>>((const unsigned int*)d_in[1]);
    split_w_kernel<<<160, 256>>>(W1, W2, Wl);
    scan_kernel<<<1, 1024>>>();
    fill_kernel<<<(NE + 255) / 256, 256>>>();

    dim3 pgrid((NN + 7) / 8);
    dim3 ggrid((NN + 127) / 128);   // 391 CTAs

    // layer 1: propagate(x) -> Ah/Al ; GEMM -> bufB (f32, relu)
    prop_kernel<true><<<pgrid, 256>>>(x);
    mma_gemm<128, true, 0, 1><<<ggrid, 256>>>(b1, nullptr);
    // layer 2: propagate(bufB) -> Ah/Al ; GEMM -> Ah/Al (bf16 split, relu)
    prop_kernel<false><<<pgrid, 256>>>(nullptr);
    mma_gemm<128, true, 1, 2><<<ggrid, 256>>>(b2, nullptr);
    // head: Ah/Al @ Wl + bl -> out
    mma_gemm<64, false, 2, 3><<<ggrid, 256>>>(bl, out);
}

// round 10
// speedup vs baseline: 1.8000x; 1.2169x over previous
#include <cuda_runtime.h>
#include <cuda_bf16.h>
#include <cstdint>

#define NN 50000
#define NE 640000
#define DD 128
#define NCLS 64
#define NB 49          // scan blocks: 49*1024 = 50176 >= NN

// ---------------- scratch (device globals) ----------------
__device__ uint4  g_Ah[(size_t)NN * 16];   // [NN][128] bf16 hi  (row = 256B = 16 uint4)
__device__ uint4  g_Al[(size_t)NN * 16];   // [NN][128] bf16 lo
__device__ float4 g_bufB[(size_t)NN * 32]; // [NN][128] f32 (layer outputs)
__device__ uint4  g_W1h[128 * 16], g_W1l[128 * 16];  // W1^T [n][k] bf16
__device__ uint4  g_W2h[128 * 16], g_W2l[128 * 16];  // W2^T
__device__ uint4  g_W3h[64 * 16],  g_W3l[64 * 16];   // Wl^T [64][128]
__device__ int4   g_cnt4[NB * 256];        // 50176 counters (16B-aligned)
__device__ int    g_bsum[NB];
__device__ int    g_bscan[NB];
__device__ int    g_off[NN + 1];
__device__ int    g_cur[NN];
__device__ float  g_dinv[NN];
__device__ int    g_col[NE];
__device__ int    g_src[NE];
__device__ int    g_dst[NE];

// ---------------- helpers ----------------
__device__ __forceinline__ uint32_t smem_u32(const void* p) {
    uint32_t a;
    asm("{ .reg .u64 t; cvta.to.shared.u64 t, %1; cvt.u32.u64 %0, t; }" : "=r"(a) : "l"(p));
    return a;
}
__device__ __forceinline__ void ldsm_x4(uint32_t& r0, uint32_t& r1, uint32_t& r2, uint32_t& r3,
                                        uint32_t addr) {
    asm volatile("ldmatrix.sync.aligned.m8n8.x4.shared.b16 {%0,%1,%2,%3}, [%4];"
                 : "=r"(r0), "=r"(r1), "=r"(r2), "=r"(r3) : "r"(addr));
}
__device__ __forceinline__ void mma_bf16(float* c, uint32_t a0, uint32_t a1, uint32_t a2,
                                         uint32_t a3, uint32_t b0, uint32_t b1) {
    asm volatile(
        "mma.sync.aligned.m16n8k16.row.col.f32.bf16.bf16.f32 "
        "{%0,%1,%2,%3}, {%4,%5,%6,%7}, {%8,%9}, {%0,%1,%2,%3};"
        : "+f"(c[0]), "+f"(c[1]), "+f"(c[2]), "+f"(c[3])
        : "r"(a0), "r"(a1), "r"(a2), "r"(a3), "r"(b0), "r"(b1));
}
__device__ __forceinline__ int warp_iscan(int v, int lane) {
    #pragma unroll
    for (int d = 1; d < 32; d <<= 1) {
        int t = __shfl_up_sync(0xffffffffu, v, d);
        if (lane >= d) v += t;
    }
    return v;
}

// ---------------- CSR build ----------------
__global__ void zero_cnt_kernel() {
    int i = blockIdx.x * blockDim.x + threadIdx.x;
    if (i < NB * 256) g_cnt4[i] = make_int4(0, 0, 0, 0);
}

// fused dtype-detect + normalize + histogram (verified)
__global__ void edges_kernel(const unsigned int* __restrict__ raw) {
    __shared__ int s_is64;
    if (threadIdx.x < 32) {
        size_t k = (size_t)threadIdx.x * (NE / 32);
        unsigned int hi = raw[2 * k + 1];
        unsigned int any = __ballot_sync(0xffffffffu, hi != 0u);
        if (threadIdx.x == 0) s_is64 = (any == 0u);
    }
    __syncthreads();
    int is64 = s_is64;
    int e = blockIdx.x * blockDim.x + threadIdx.x;
    if (e >= NE) return;
    const int* raw32 = (const int*)raw;
    int s, d;
    if (is64) { s = raw32[2 * (size_t)e]; d = raw32[2 * ((size_t)NE + e)]; }
    else      { s = raw32[e];             d = raw32[NE + e]; }
    s = min(max(s, 0), NN - 1);
    d = min(max(d, 0), NN - 1);
    g_src[e] = s;
    g_dst[e] = d;
    atomicAdd(&((int*)g_cnt4)[d], 1);
}

// ---- multi-block scan: phase 1 (per-block reduce) ----
__global__ void scan1_kernel() {
    __shared__ int wsum[8];
    int t = threadIdx.x, b = blockIdx.x;
    int lane = t & 31, w = t >> 5;
    int4 v = g_cnt4[b * 256 + t];
    int s = v.x + v.y + v.z + v.w;
    int inc = warp_iscan(s, lane);
    if (lane == 31) wsum[w] = inc;
    __syncthreads();
    if (t == 0) {
        int tot = 0;
        #pragma unroll
        for (int i = 0; i < 8; ++i) tot += wsum[i];
        g_bsum[b] = tot;
    }
}

// ---- phase 2: scan 49 block sums (2 warps) ----
__global__ void scan2_kernel() {
    __shared__ int w0tot;
    int t = threadIdx.x, lane = t & 31, w = t >> 5;
    int s = (t < NB) ? g_bsum[t] : 0;
    int inc = warp_iscan(s, lane);
    if (w == 0 && lane == 31) w0tot = inc;
    __syncthreads();
    int excl = inc - s + (w ? w0tot : 0);
    if (t < NB) g_bscan[t] = excl;
    if (t == NB - 1) g_off[NN] = excl + s;
}

// ---- phase 3: per-block rescan + carry; emit off/cur/dinv ----
__global__ void scan3_kernel() {
    __shared__ int wsum[8];
    int t = threadIdx.x, b = blockIdx.x;
    int lane = t & 31, w = t >> 5;
    int4 v = g_cnt4[b * 256 + t];
    int s = v.x + v.y + v.z + v.w;
    int inc = warp_iscan(s, lane);
    if (lane == 31) wsum[w] = inc;
    __syncthreads();
    int woff = 0;
    #pragma unroll
    for (int i = 0; i < 8; ++i) if (i < w) woff += wsum[i];
    int excl = g_bscan[b] + woff + inc - s;
    int i0 = (b * 256 + t) * 4;
    int e0 = excl, e1 = e0 + v.x, e2 = e1 + v.y, e3 = e2 + v.z;
    if (i0 + 0 < NN) { g_off[i0 + 0] = e0; g_cur[i0 + 0] = e0; g_dinv[i0 + 0] = rsqrtf((float)(v.x + 1)); }
    if (i0 + 1 < NN) { g_off[i0 + 1] = e1; g_cur[i0 + 1] = e1; g_dinv[i0 + 1] = rsqrtf((float)(v.y + 1)); }
    if (i0 + 2 < NN) { g_off[i0 + 2] = e2; g_cur[i0 + 2] = e2; g_dinv[i0 + 2] = rsqrtf((float)(v.z + 1)); }
    if (i0 + 3 < NN) { g_off[i0 + 3] = e3; g_cur[i0 + 3] = e3; g_dinv[i0 + 3] = rsqrtf((float)(v.w + 1)); }
}

__global__ void fill_kernel() {
    int e = blockIdx.x * blockDim.x + threadIdx.x;
    if (e < NE) {
        int p = atomicAdd(&g_cur[g_dst[e]], 1);
        g_col[p] = g_src[e];
    }
}

// ---------------- weight split: W[k][n] f32 -> W^T[n][k] bf16 hi/lo ----------------
__global__ void split_w_kernel(const float* __restrict__ W1, const float* __restrict__ W2,
                               const float* __restrict__ W3) {
    int i = blockIdx.x * blockDim.x + threadIdx.x;
    float v; __nv_bfloat16* dh; __nv_bfloat16* dl; int n, k;
    if (i < 16384) {
        v = W1[i]; k = i >> 7; n = i & 127;
        dh = (__nv_bfloat16*)g_W1h; dl = (__nv_bfloat16*)g_W1l;
    } else if (i < 32768) {
        int j = i - 16384;
        v = W2[j]; k = j >> 7; n = j & 127;
        dh = (__nv_bfloat16*)g_W2h; dl = (__nv_bfloat16*)g_W2l;
    } else if (i < 40960) {
        int j = i - 32768;
        v = W3[j]; k = j >> 6; n = j & 63;
        dh = (__nv_bfloat16*)g_W3h; dl = (__nv_bfloat16*)g_W3l;
    } else return;
    __nv_bfloat16 h = __float2bfloat16(v);
    __nv_bfloat16 l = __float2bfloat16(v - __bfloat162float(h));
    dh[n * 128 + k] = h;
    dl[n * 128 + k] = l;
}

// ---------------- sparse propagate -> bf16 hi/lo split output ----------------
template<bool FROM_X>
__global__ void prop_kernel(const float* __restrict__ xin) {
    int warp = (blockIdx.x * blockDim.x + threadIdx.x) >> 5;
    int lane = threadIdx.x & 31;
    if (warp >= NN) return;
    const float4* X4 = FROM_X ? (const float4*)xin : (const float4*)g_bufB;
    int i = warp;
    float di = g_dinv[i];
    float4 v = X4[(size_t)i * 32 + lane];
    float ax = di * v.x, ay = di * v.y, az = di * v.z, aw = di * v.w;
    int e  = g_off[i];
    int e1 = g_off[i + 1];
    for (; e + 4 <= e1; e += 4) {
        int s0 = g_col[e + 0], s1 = g_col[e + 1], s2 = g_col[e + 2], s3 = g_col[e + 3];
        float w0 = g_dinv[s0], w1 = g_dinv[s1], w2 = g_dinv[s2], w3 = g_dinv[s3];
        float4 v0 = X4[(size_t)s0 * 32 + lane];
        float4 v1 = X4[(size_t)s1 * 32 + lane];
        float4 v2 = X4[(size_t)s2 * 32 + lane];
        float4 v3 = X4[(size_t)s3 * 32 + lane];
        ax += w0 * v0.x + w1 * v1.x + w2 * v2.x + w3 * v3.x;
        ay += w0 * v0.y + w1 * v1.y + w2 * v2.y + w3 * v3.y;
        az += w0 * v0.z + w1 * v1.z + w2 * v2.z + w3 * v3.z;
        aw += w0 * v0.w + w1 * v1.w + w2 * v2.w + w3 * v3.w;
    }
    for (; e < e1; ++e) {
        int s = g_col[e];
        float w = g_dinv[s];
        float4 vv = X4[(size_t)s * 32 + lane];
        ax += w * vv.x; ay += w * vv.y; az += w * vv.z; aw += w * vv.w;
    }
    ax *= di; ay *= di; az *= di; aw *= di;
    __nv_bfloat16 hx = __float2bfloat16(ax), hy = __float2bfloat16(ay);
    __nv_bfloat16 hz = __float2bfloat16(az), hw = __float2bfloat16(aw);
    __nv_bfloat16 lx = __float2bfloat16(ax - __bfloat162float(hx));
    __nv_bfloat16 ly = __float2bfloat16(ay - __bfloat162float(hy));
    __nv_bfloat16 lz = __float2bfloat16(az - __bfloat162float(hz));
    __nv_bfloat16 lw = __float2bfloat16(aw - __bfloat162float(hw));
    uint2 hv, lv;
    hv.x = ((uint32_t)__bfloat16_as_ushort(hy) << 16) | __bfloat16_as_ushort(hx);
    hv.y = ((uint32_t)__bfloat16_as_ushort(hw) << 16) | __bfloat16_as_ushort(hz);
    lv.x = ((uint32_t)__bfloat16_as_ushort(ly) << 16) | __bfloat16_as_ushort(lx);
    lv.y = ((uint32_t)__bfloat16_as_ushort(lw) << 16) | __bfloat16_as_ushort(lz);
    ((uint2*)g_Ah)[(size_t)i * 32 + lane] = hv;
    ((uint2*)g_Al)[(size_t)i * 32 + lane] = lv;
}

// ---------------- HMMA bf16 3-term GEMM (verified R8) ----------------
template<int N, bool RELU, int OUT, int LAY>
__global__ void __launch_bounds__(256) mma_gemm(const float* __restrict__ bias,
                                                float* __restrict__ outp) {
    constexpr int NT = N / 8;
    __shared__ uint4 sAh[128 * 4], sAl[128 * 4];
    __shared__ uint4 sBh[N * 4],   sBl[N * 4];

    const uint4* Wh = (LAY == 1) ? g_W1h : (LAY == 2) ? g_W2h : g_W3h;
    const uint4* Wl = (LAY == 1) ? g_W1l : (LAY == 2) ? g_W2l : g_W3l;

    int tid = threadIdx.x;
    int wid = tid >> 5;
    int lid = tid & 31;
    int m0  = blockIdx.x * 128;

    float acc[NT][4];
    #pragma unroll
    for (int t = 0; t < NT; ++t)
        #pragma unroll
        for (int j = 0; j < 4; ++j) acc[t][j] = 0.f;

    uint32_t sAh_b = smem_u32(sAh), sAl_b = smem_u32(sAl);
    uint32_t sBh_b = smem_u32(sBh), sBl_b = smem_u32(sBl);

    uint32_t a_row  = lid & 15;
    uint32_t a_half = lid >> 4;
    uint32_t a_x    = (a_row >> 1) & 3;
    uint32_t a_base = (wid * 16 + a_row) * 64;
    uint32_t b_c    = (lid & 7) + ((lid >> 4) & 1) * 8;
    uint32_t b_half = (lid >> 3) & 1;
    uint32_t b_x    = (b_c >> 1) & 3;
    uint32_t b_base = b_c * 64;

    for (int c = 0; c < 4; ++c) {
        #pragma unroll
        for (int f = tid; f < 128 * 4; f += 256) {
            int row = f >> 2, ch = f & 3;
            int gr = m0 + row;
            uint4 vh = make_uint4(0, 0, 0, 0), vl = vh;
            if (gr < NN) {
                size_t gi = (size_t)gr * 16 + c * 4 + ch;
                vh = g_Ah[gi]; vl = g_Al[gi];
            }
            int du = row * 4 + (ch ^ ((row >> 1) & 3));
            sAh[du] = vh; sAl[du] = vl;
        }
        #pragma unroll
        for (int f = tid; f < N * 4; f += 256) {
            int row = f >> 2, ch = f & 3;
            size_t gi = (size_t)row * 16 + c * 4 + ch;
            int du = row * 4 + (ch ^ ((row >> 1) & 3));
            sBh[du] = Wh[gi]; sBl[du] = Wl[gi];
        }
        __syncthreads();

        #pragma unroll
        for (int ks = 0; ks < 2; ++ks) {
            uint32_t aoff = a_base + (((ks * 2 + a_half) ^ a_x) << 4);
            uint32_t ah0, ah1, ah2, ah3, al0, al1, al2, al3;
            ldsm_x4(ah0, ah1, ah2, ah3, sAh_b + aoff);
            ldsm_x4(al0, al1, al2, al3, sAl_b + aoff);
            #pragma unroll
            for (int jp = 0; jp < NT / 2; ++jp) {
                uint32_t boff = jp * 1024 + b_base + (((ks * 2 + b_half) ^ b_x) << 4);
                uint32_t bh0, bh1, bh2, bh3, bl0, bl1, bl2, bl3;
                ldsm_x4(bh0, bh1, bh2, bh3, sBh_b + boff);
                mma_bf16(acc[2 * jp],     ah0, ah1, ah2, ah3, bh0, bh1);
                mma_bf16(acc[2 * jp + 1], ah0, ah1, ah2, ah3, bh2, bh3);
                mma_bf16(acc[2 * jp],     al0, al1, al2, al3, bh0, bh1);
                mma_bf16(acc[2 * jp + 1], al0, al1, al2, al3, bh2, bh3);
                ldsm_x4(bl0, bl1, bl2, bl3, sBl_b + boff);
                mma_bf16(acc[2 * jp],     ah0, ah1, ah2, ah3, bl0, bl1);
                mma_bf16(acc[2 * jp + 1], ah0, ah1, ah2, ah3, bl2, bl3);
            }
        }
        __syncthreads();
    }

    int g = lid >> 2, q = lid & 3;
    int r0 = m0 + wid * 16 + g;
    int r1 = r0 + 8;
    #pragma unroll
    for (int nt = 0; nt < NT; ++nt) {
        int col = nt * 8 + 2 * q;
        float2 bb = *(const float2*)&bias[col];
        float v0 = acc[nt][0] + bb.x, v1 = acc[nt][1] + bb.y;
        float v2 = acc[nt][2] + bb.x, v3 = acc[nt][3] + bb.y;
        if (RELU) {
            v0 = fmaxf(v0, 0.f); v1 = fmaxf(v1, 0.f);
            v2 = fmaxf(v2, 0.f); v3 = fmaxf(v3, 0.f);
        }
        if (OUT == 1) {
            __nv_bfloat16 h0 = __float2bfloat16(v0), h1 = __float2bfloat16(v1);
            __nv_bfloat16 h2 = __float2bfloat16(v2), h3 = __float2bfloat16(v3);
            ushort2 hp0, hp1, lp0, lp1;
            hp0.x = __bfloat16_as_ushort(h0); hp0.y = __bfloat16_as_ushort(h1);
            hp1.x = __bfloat16_as_ushort(h2); hp1.y = __bfloat16_as_ushort(h3);
            lp0.x = __bfloat16_as_ushort(__float2bfloat16(v0 - __bfloat162float(h0)));
            lp0.y = __bfloat16_as_ushort(__float2bfloat16(v1 - __bfloat162float(h1)));
            lp1.x = __bfloat16_as_ushort(__float2bfloat16(v2 - __bfloat162float(h2)));
            lp1.y = __bfloat16_as_ushort(__float2bfloat16(v3 - __bfloat162float(h3)));
            if (r0 < NN) {
                *(ushort2*)((__nv_bfloat16*)g_Ah + (size_t)r0 * 128 + col) = hp0;
                *(ushort2*)((__nv_bfloat16*)g_Al + (size_t)r0 * 128 + col) = lp0;
            }
            if (r1 < NN) {
                *(ushort2*)((__nv_bfloat16*)g_Ah + (size_t)r1 * 128 + col) = hp1;
                *(ushort2*)((__nv_bfloat16*)g_Al + (size_t)r1 * 128 + col) = lp1;
            }
        } else {
            float* C = (OUT == 2) ? outp : (float*)g_bufB;
            if (r0 < NN) *(float2*)&C[(size_t)r0 * N + col] = make_float2(v0, v1);
            if (r1 < NN) *(float2*)&C[(size_t)r1 * N + col] = make_float2(v2, v3);
        }
    }
}

// ---------------- launch ----------------
extern "C" void kernel_launch(void* const* d_in, const int* in_sizes, int n_in,
                              void* d_out, int out_size) {
    const float* x  = (const float*)d_in[0];
    const float* W1 = (const float*)d_in[2];
    const float* b1 = (const float*)d_in[3];
    const float* W2 = (const float*)d_in[4];
    const float* b2 = (const float*)d_in[5];
    const float* Wl = (const float*)d_in[6];
    const float* bl = (const float*)d_in[7];
    float*       out = (float*)d_out;

    // CSR build + weight split
    zero_cnt_kernel<<<NB, 256>>>();
    edges_kernel<<<(NE + 255) / 256, 256>>>((const unsigned int*)d_in[1]);
    split_w_kernel<<<160, 256>>>(W1, W2, Wl);
    scan1_kernel<<<NB, 256>>>();
    scan2_kernel<<<1, 64>>>();
    scan3_kernel<<<NB, 256>>>();
    fill_kernel<<<(NE + 255) / 256, 256>>>();

    dim3 pgrid((NN + 7) / 8);
    dim3 ggrid((NN + 127) / 128);   // 391 CTAs

    // layer 1: propagate(x) -> Ah/Al ; GEMM -> bufB (f32, relu)
    prop_kernel<true><<<pgrid, 256>>>(x);
    mma_gemm<128, true, 0, 1><<<ggrid, 256>>>(b1, nullptr);
    // layer 2: propagate(bufB) -> Ah/Al ; GEMM -> Ah/Al (bf16 split, relu)
    prop_kernel<false><<<pgrid, 256>>>(nullptr);
    mma_gemm<128, true, 1, 2><<<ggrid, 256>>>(b2, nullptr);
    // head: Ah/Al @ Wl + bl -> out
    mma_gemm<64, false, 2, 3><<<ggrid, 256>>>(bl, out);
}